// round 15
// baseline (speedup 1.0000x reference)
#include <cuda_runtime.h>
#include <math.h>

// Fixed shapes: B=32, S=128, V=8, T=66 -> 256 independent sequences.
// One block (320 thr) per TWO sequences; two disjoint 5-warp barrier domains:
//   domain 0 (warps 0-4): FORWARD chains of seqA and seqB (shared eF regs)
//   domain 1 (warps 5-9): BACKWARD chains of seqA and seqB (shared eB regs)
// Each interval advances both seqs one step in each domain (depth 63).
// Meet once per seq: Z = alpha_63^T M w_64.
#define TT   66
#define SS   128
#define NSEQ 256
#define NBLK 128
#define NTHR 320
#define USTR 72

typedef unsigned long long ull;

__device__ float        g_partial[NSEQ];
__device__ unsigned int g_count = 0;

static __device__ __forceinline__ ull pk2(float lo, float hi) {
    ull r; asm("mov.b64 %0, {%1,%2};" : "=l"(r) : "f"(lo), "f"(hi)); return r;
}
static __device__ __forceinline__ void fma2(ull& d, ull a, ull b) {
    asm("fma.rn.f32x2 %0, %1, %2, %0;" : "+l"(d) : "l"(a), "l"(b));
}
static __device__ __forceinline__ void add2(ull& d, ull a, ull b) {
    asm("add.rn.f32x2 %0, %1, %2;" : "=l"(d) : "l"(a), "l"(b));
}
static __device__ __forceinline__ float2 upk2(ull v) {
    float lo, hi; asm("mov.b64 {%0,%1}, %2;" : "=f"(lo), "=f"(hi) : "l"(v));
    return make_float2(lo, hi);
}
#define DBAR(dd) asm volatile("bar.sync %0, 160;" :: "r"((dd) + 1) : "memory")

// smem floats: esh 2*SS*TT + ubuf 8*USTR + wmax 20 + sL 4 + sSc 4
//              + sgold 8 + sws 10 + wred 8 + flag pad 2
#define SMEM_FLOATS (2*SS*TT + 8*USTR + 20 + 4 + 4 + 8 + 10 + 8 + 2)
#define SMEM_BYTES  (SMEM_FLOATS*4)

__global__ void __launch_bounds__(NTHR) crf_kernel(
    const float* __restrict__ score,       // [B,S,S,T]
    const float* __restrict__ trans,       // [T,T]
    const float* __restrict__ startT,      // [T]
    const float* __restrict__ endT,        // [T]
    const int*   __restrict__ v_label,     // [B*V]
    const int*   __restrict__ role_label,  // [B*V][S]
    float*       __restrict__ out)
{
    extern __shared__ __align__(16) float sm[];
    float* esh   = sm;                       // [2 seq][SS*TT] exp(emissions)
    float* ubuf  = esh + 2*SS*TT;            // [seq][dir][pp][USTR]
    float* wmax  = ubuf + 8*USTR;            // [dir][seq][5]
    float* sLv   = wmax + 20;                // [dir][seq]
    float* sScv  = sLv + 4;                  // [dir][seq]
    float* sgold = sScv + 4;                 // [8]
    float* sws   = sgold + 8;                // [seq][5]
    float* wred  = sws + 10;                 // [8]
    int*   sflag = (int*)(wred + 8);

    const int tid  = threadIdx.x;
    const int lane = tid & 31;
    const int wid  = tid >> 5;
    const int d    = (wid >= 5) ? 1 : 0;     // 0 = forward, 1 = backward
    const int ts   = tid - d*160;            // slot within domain
    const int w5   = ts >> 5;                // warp within domain (0..4)
    const bool act = (ts < 132);
    const int cc   = act ? (ts >> 1) : 0;    // state (column fwd / row bwd)
    const int h    = ts & 1;                 // half
    const int loc  = cc + ((cc >= 32) ? 4 : 0);

    const int sA = blockIdx.x*2;
    const int sB = sA + 1;
    const float* erowA = score + ((size_t)((sA >> 3)*SS + __ldg(&v_label[sA])))*SS*TT;
    const float* erowB = score + ((size_t)((sB >> 3)*SS + __ldg(&v_label[sB])))*SS*TT;

    #define SLAB(p, dd, pp) (ubuf + (((p)*2 + (dd))*2 + (pp))*USTR)

    // ---- gold paths: warps 0-7 (one position per thread) ----
    if (wid < 8) {
        int p = wid >> 2;
        int s = (wid & 3)*32 + lane;
        int seq = sA + p;
        const float* er = p ? erowB : erowA;
        int tg = __ldg(&role_label[seq*SS + s]);
        float gg = __ldg(&er[s*TT + tg]);
        if (s < SS-1) gg += __ldg(&trans[tg*TT + __ldg(&role_label[seq*SS + s + 1])]);
        else          gg += __ldg(&endT[tg]);
        if (s == 0)   gg += __ldg(&startT[tg]);
        #pragma unroll
        for (int o = 16; o; o >>= 1) gg += __shfl_xor_sync(~0u, gg, o);
        if (lane == 0) sgold[wid] = gg;
    }

    // ---- stage exp(emissions) for both sequences ----
    {
        const float4* srcA = (const float4*)erowA;
        const float4* srcB = (const float4*)erowB;
        float4* dstA = (float4*)esh;
        float4* dstB = (float4*)(esh + SS*TT);
        #pragma unroll 2
        for (int k = tid; k < (SS*TT)/4; k += NTHR) {
            float4 va = __ldg(&srcA[k]);
            float4 vb = __ldg(&srcB[k]);
            va.x = __expf(va.x); va.y = __expf(va.y); va.z = __expf(va.z); va.w = __expf(va.w);
            vb.x = __expf(vb.x); vb.y = __expf(vb.y); vb.z = __expf(vb.z); vb.w = __expf(vb.w);
            dstA[k] = va;
            dstB[k] = vb;
        }
    }

    // ---- exp(trans) regs: fwd = COLUMN cc over row-half; bwd = ROW cc over
    //      col-half. SHARED by both sequences of this block. ----
    ull e[17];
    if (act) {
        if (d == 0) {
            #pragma unroll
            for (int k = 0; k < 16; k++) {
                int rr = h*32 + 2*k;
                e[k] = pk2(__expf(__ldg(&trans[rr*TT + cc])),
                           __expf(__ldg(&trans[(rr+1)*TT + cc])));
            }
            e[16] = (h == 0) ? pk2(__expf(__ldg(&trans[64*TT + cc])),
                                   __expf(__ldg(&trans[65*TT + cc]))) : 0ULL;
        } else {
            #pragma unroll
            for (int k = 0; k < 16; k++) {
                float2 f = __ldg((const float2*)(trans + cc*TT + h*32 + 2*k));
                e[k] = pk2(__expf(f.x), __expf(f.y));
            }
            if (h == 0) {
                float2 f = __ldg((const float2*)(trans + cc*TT + 64));
                e[16] = pk2(__expf(f.x), __expf(f.y));
            } else e[16] = 0ULL;
        }
    } else {
        #pragma unroll
        for (int k = 0; k < 17; k++) e[k] = 0ULL;
    }
    const float bis = act ? __expf(__ldg(d ? &endT[cc] : &startT[cc])) : 0.f;

    __syncthreads();   // esh staged (both domains consume it)

    // ---- init both chains of this domain ----
    const float* eA0 = esh + (d ? 127*TT : 0);
    const float* eB0 = esh + SS*TT + (d ? 127*TT : 0);
    float rA = act ? (bis * eA0[cc]) : 0.f;
    float rB = act ? (bis * eB0[cc]) : 0.f;
    if (act && h == 0) { SLAB(0,d,0)[loc] = rA; SLAB(1,d,0)[loc] = rB; }
    {
        float mA = rA, mB = rB;
        #pragma unroll
        for (int o = 16; o; o >>= 1) {
            mA = fmaxf(mA, __shfl_xor_sync(~0u, mA, o));
            mB = fmaxf(mB, __shfl_xor_sync(~0u, mB, o));
        }
        if (lane == 0) { wmax[(d*2+0)*5 + w5] = mA; wmax[(d*2+1)*5 + w5] = mB; }
    }
    DBAR(d);
    #define CMB(pp) fmaxf(fmaxf(fmaxf(wmax[(d*2+(pp))*5+0], wmax[(d*2+(pp))*5+1]), \
                          fmaxf(wmax[(d*2+(pp))*5+2], wmax[(d*2+(pp))*5+3])), wmax[(d*2+(pp))*5+4])
    float mA2 = CMB(0), mB2 = CMB(1);
    float scA = __fdividef(1.0f, mA2);
    float scB = __fdividef(1.0f, mB2);
    float LA  = __logf(mA2);
    float LB  = __logf(mB2);

    float* ucA = SLAB(0,d,0); float* unA = SLAB(0,d,1);
    float* ucB = SLAB(1,d,0); float* unB = SLAB(1,d,1);
    const int dE = d ? -TT : TT;
    const float* emA = esh + (d ? 126*TT : TT);
    const float* emB = esh + SS*TT + (d ? 126*TT : TT);

    // ---- one chain-step (half-dot + pair combine), no barrier inside ----
    auto STEP1 = [&](const float* uc, float* un, const float* emrow,
                     float scale, float& r) {
        float em = emrow[cc];
        const ulonglong2* u2 = (const ulonglong2*)(uc + h*36);
        ull d0 = 0, d1 = 0;
        #pragma unroll
        for (int i = 0; i < 8; i++) {
            ulonglong2 v = u2[i];
            fma2(d0, v.x, e[2*i]);
            fma2(d1, v.y, e[2*i+1]);
        }
        ull lastp = *(const ull*)(uc + 68);
        fma2(d0, lastp, e[16]);
        add2(d0, d0, d1);
        float2 f = upk2(d0);
        float s = f.x + f.y;
        s += __shfl_xor_sync(~0u, s, 1);
        r = act ? s * (scale * em) : 0.f;
        if (act && h == 0) un[loc] = r;
    };

    // ---- 63 intervals: each advances BOTH seqs; renorm every 8 ----
    for (int grp = 0; grp < 8; grp++) {
        const int n = (grp == 7) ? 7 : 8;
        #pragma unroll 8
        for (int q = 0; q < n; q++) {
            STEP1(ucA, unA, emA, (q == 0) ? scA : 1.0f, rA);
            STEP1(ucB, unB, emB, (q == 0) ? scB : 1.0f, rB);
            if (q == n-1) {
                float mA = rA, mB = rB;
                #pragma unroll
                for (int o = 16; o; o >>= 1) {
                    mA = fmaxf(mA, __shfl_xor_sync(~0u, mA, o));
                    mB = fmaxf(mB, __shfl_xor_sync(~0u, mB, o));
                }
                if (lane == 0) { wmax[(d*2+0)*5 + w5] = mA; wmax[(d*2+1)*5 + w5] = mB; }
            }
            DBAR(d);
            float* tp;
            tp = ucA; ucA = unA; unA = tp;
            tp = ucB; ucB = unB; unB = tp;
            emA += dE; emB += dE;
        }
        mA2 = CMB(0); mB2 = CMB(1);
        scA = __fdividef(1.0f, mA2);
        scB = __fdividef(1.0f, mB2);
        LA += __logf(mA2);
        LB += __logf(mB2);
    }
    // invariant: actual = stored * exp(L) * sc   (sc pending)

    if (ts == 0) {
        sLv[d*2+0] = LA; sLv[d*2+1] = LB;
        sScv[d*2+0] = scA; sScv[d*2+1] = scB;
    }
    __syncthreads();   // domains meet

    // ---- epilogue (forward domain): Z_p = sum_c (M^T alpha63)_c * w64_p[c] ----
    if (d == 0) {
        #pragma unroll
        for (int p = 0; p < 2; p++) {
            const float* ua = (p == 0) ? ucA : ucB;     // final alpha slab
            const float* uw = SLAB(p, 1, 1);            // final w slab (63 steps -> 1)
            const float scF = (p == 0) ? scA : scB;
            const float scBk = sScv[1*2 + p];
            const ulonglong2* u2 = (const ulonglong2*)(ua + h*36);
            ull d0 = 0, d1 = 0;
            #pragma unroll
            for (int i = 0; i < 8; i++) {
                ulonglong2 v = u2[i];
                fma2(d0, v.x, e[2*i]);
                fma2(d1, v.y, e[2*i+1]);
            }
            ull lastp = *(const ull*)(ua + 68);
            fma2(d0, lastp, e[16]);
            add2(d0, d0, d1);
            float2 f = upk2(d0);
            float s = f.x + f.y;
            s += __shfl_xor_sync(~0u, s, 1);
            float contrib = 0.f;
            if (act && h == 0) contrib = (s * scF) * (uw[loc] * scBk);
            #pragma unroll
            for (int o = 16; o; o >>= 1) contrib += __shfl_xor_sync(~0u, contrib, o);
            if (lane == 0) sws[p*5 + w5] = contrib;
        }
    }
    __syncthreads();

    if (tid < 2) {
        int p = tid;
        float ws = (((sws[p*5+0] + sws[p*5+1]) + (sws[p*5+2] + sws[p*5+3])) + sws[p*5+4]);
        float gt = ((sgold[p*4+0] + sgold[p*4+1]) + (sgold[p*4+2] + sgold[p*4+3]));
        float logZ = __logf(ws) + sLv[0*2+p] + sLv[1*2+p];
        __stcg(&g_partial[sA + p], logZ - gt);
    }
    __threadfence();
    __syncthreads();
    if (tid == 0) {
        unsigned c0 = atomicAdd(&g_count, 1u);
        *sflag = (c0 == NBLK - 1) ? 1 : 0;
    }
    __syncthreads();

    // ---- fused final reduction in the last block ----
    if (*sflag) {
        if (tid < 128) {
            float v = __ldcg(&g_partial[tid]) + __ldcg(&g_partial[tid + 128]);
            #pragma unroll
            for (int o = 16; o; o >>= 1) v += __shfl_xor_sync(~0u, v, o);
            if (lane == 0) wred[wid] = v;
        }
        __syncthreads();
        if (tid == 0) {
            out[0] = ((wred[0] + wred[1]) + (wred[2] + wred[3]))
                     * (1.0f / (float)NSEQ);
            g_count = 0;                       // reset for next graph replay
        }
    }
}

extern "C" void kernel_launch(void* const* d_in, const int* in_sizes, int n_in,
                              void* d_out, int out_size) {
    const float* score      = (const float*)d_in[0];
    const float* trans      = (const float*)d_in[1];
    const float* startT     = (const float*)d_in[2];
    const float* endT       = (const float*)d_in[3];
    const int*   v_label    = (const int*)d_in[4];
    const int*   role_label = (const int*)d_in[5];
    float* out = (float*)d_out;

    cudaFuncSetAttribute(crf_kernel,
                         cudaFuncAttributeMaxDynamicSharedMemorySize, SMEM_BYTES);

    crf_kernel<<<NBLK, NTHR, SMEM_BYTES>>>(
        score, trans, startT, endT, v_label, role_label, out);
}

// round 16
// speedup vs baseline: 1.3379x; 1.3379x over previous
#include <cuda_runtime.h>
#include <math.h>

// Fixed shapes: B=32, S=128, V=8, T=66 -> 256 independent sequences.
// One block (64 thr) per sequence, TWO independent warp-synchronous chains:
//   warp 0: forward  alpha_0 -> alpha_63   warp 1: backward w_127 -> w_64
// u pairs 0..31 via smem broadcast LDS; pair 32 (states 64/65) register-resident.
// Renorm butterfly DEFERRED into the next step (overlaps fma stream).
// No __syncwarp in the loop (converged-warp STS->LDS order + CFENCE).
// Meet once: Z = (alpha_63 M) . w_64.
#define TT   66
#define SS   128
#define NSEQ 256
#define NTHR 64
#define USTR 72

typedef unsigned long long ull;

__device__ float        g_partial[NSEQ];
__device__ unsigned int g_count = 0;

static __device__ __forceinline__ ull pk2(float lo, float hi) {
    ull r; asm("mov.b64 %0, {%1,%2};" : "=l"(r) : "f"(lo), "f"(hi)); return r;
}
static __device__ __forceinline__ void fma2(ull& d, ull a, ull b) {
    asm("fma.rn.f32x2 %0, %1, %2, %0;" : "+l"(d) : "l"(a), "l"(b));
}
static __device__ __forceinline__ void add2(ull& d, ull a, ull b) {
    asm("add.rn.f32x2 %0, %1, %2;" : "=l"(d) : "l"(a), "l"(b));
}
static __device__ __forceinline__ float2 upk2(ull v) {
    float lo, hi; asm("mov.b64 {%0,%1}, %2;" : "=f"(lo), "=f"(hi) : "l"(v));
    return make_float2(lo, hi);
}
#define CFENCE() asm volatile("" ::: "memory")

__global__ void __launch_bounds__(NTHR) crf_kernel(
    const float* __restrict__ score,       // [B,S,S,T]
    const float* __restrict__ trans,       // [T,T]
    const float* __restrict__ startT,      // [T]
    const float* __restrict__ endT,        // [T]
    const int*   __restrict__ v_label,     // [B*V]
    const int*   __restrict__ role_label,  // [B*V][S]
    float*       __restrict__ out)
{
    __shared__ __align__(16) float esh[2][64*TT];   // [warp][64 rows][66] exp(emis)
    __shared__ __align__(16) float ubuf[2][2][USTR];// [warp][pingpong] (pairs 0..31)
    __shared__ __align__(16) float wslab[68];       // warp1 final w_64 (raw)
    __shared__ float sL[2], sgold[2], swsum, wred[2];
    __shared__ int   sflag;

    const int tid  = threadIdx.x;
    const int lane = tid & 31;
    const int w    = tid >> 5;             // 0 = forward, 1 = backward
    const int seq  = blockIdx.x;
    const int vr   = __ldg(&v_label[seq]);
    const float* erow = score + ((size_t)((seq >> 3)*SS + vr))*SS*TT;

    // ---- gold path: 2 positions per thread ----
    float gold = 0.f;
    #pragma unroll
    for (int p = 0; p < 2; p++) {
        int s  = tid + 64*p;
        int tg = __ldg(&role_label[seq*SS + s]);
        float gg = __ldg(&erow[s*TT + tg]);
        if (s < SS-1) gg += __ldg(&trans[tg*TT + __ldg(&role_label[seq*SS + s + 1])]);
        else          gg += __ldg(&endT[tg]);
        if (s == 0)   gg += __ldg(&startT[tg]);
        gold += gg;
    }
    #pragma unroll
    for (int o = 16; o; o >>= 1) gold += __shfl_xor_sync(~0u, gold, o);
    if (lane == 0) sgold[w] = gold;

    // ---- stage my warp's 64 emission rows, fused with exp ----
    {
        const float4* src = (const float4*)(erow + (w ? 64*TT : 0));
        float4*       dst = (float4*)esh[w];
        #pragma unroll 3
        for (int k = lane; k < (64*TT)/4; k += 32) {
            float4 v = __ldg(&src[k]);
            v.x = __expf(v.x); v.y = __expf(v.y);
            v.z = __expf(v.z); v.w = __expf(v.w);
            dst[k] = v;
        }
    }

    // ---- E registers (dual-interleave); direction per warp ----
    ull eA[33], eB[33], xA[4], xB[4];
    float cx0, cx1, cy0, cy1;
    const int g = lane & 7;
    if (w == 0) {
        #pragma unroll
        for (int m = 0; m < 33; m++) {
            float2 f0 = __ldg((const float2*)(trans + (2*m  )*TT) + lane);
            float2 f1 = __ldg((const float2*)(trans + (2*m+1)*TT) + lane);
            float a = __expf(f0.x), bq = __expf(f0.y);
            float c = __expf(f1.x), d  = __expf(f1.y);
            eA[m] = pk2(a, d);
            eB[m] = pk2(bq, c);
        }
        #pragma unroll
        for (int q = 0; q < 4; q++) {
            int rr = 2*(4*g + q);
            float2 h0 = __ldg((const float2*)(trans + rr*TT + 64));
            float2 h1 = __ldg((const float2*)(trans + (rr+1)*TT + 64));
            xA[q] = pk2(__expf(h0.x), __expf(h1.y));
            xB[q] = pk2(__expf(h0.y), __expf(h1.x));
        }
        float2 k0 = __ldg((const float2*)(trans + 64*TT + 64));
        float2 k1 = __ldg((const float2*)(trans + 65*TT + 64));
        cx0 = __expf(k0.x); cx1 = __expf(k1.x);
        cy0 = __expf(k0.y); cy1 = __expf(k1.y);
    } else {
        const float* row0 = trans + (2*lane    )*TT;
        const float* row1 = trans + (2*lane + 1)*TT;
        #pragma unroll
        for (int m = 0; m < 33; m++) {
            float2 f0 = __ldg((const float2*)row0 + m);
            float2 f1 = __ldg((const float2*)row1 + m);
            float a = __expf(f0.x), bq = __expf(f0.y);
            float c = __expf(f1.x), d  = __expf(f1.y);
            eA[m] = pk2(a, d);
            eB[m] = pk2(c, bq);
        }
        #pragma unroll
        for (int q = 0; q < 4; q++) {
            int rr = 2*(4*g + q);
            float2 h0 = __ldg((const float2*)(trans + 64*TT + rr));
            float2 h1 = __ldg((const float2*)(trans + 65*TT + rr));
            xA[q] = pk2(__expf(h0.x), __expf(h1.y));
            xB[q] = pk2(__expf(h1.x), __expf(h0.y));
        }
        float2 k0 = __ldg((const float2*)(trans + 64*TT + 64));
        float2 k1 = __ldg((const float2*)(trans + 65*TT + 64));
        cx0 = __expf(k0.x); cx1 = __expf(k0.y);
        cy0 = __expf(k1.x); cy1 = __expf(k1.y);
    }

    float2 bc = w ? __ldg((const float2*)endT + lane) : __ldg((const float2*)startT + lane);
    float2 bx = w ? __ldg((const float2*)(endT + 64)) : __ldg((const float2*)(startT + 64));

    __syncwarp();

    // ---- init: pairs in smem, pair 32 register-resident (all lanes) ----
    const float* e0 = esh[w] + (w ? 63*TT : 0);
    float r0   = __expf(bc.x) * e0[2*lane];
    float r1   = __expf(bc.y) * e0[2*lane + 1];
    float x64v = __expf(bx.x) * e0[64];
    float x65v = __expf(bx.y) * e0[65];
    float* uc = ubuf[w][0];
    float* un = ubuf[w][1];
    ((float2*)uc)[lane] = make_float2(r0, r1);

    // local-only max; the warp butterfly happens INSIDE the next step
    float mmp = fmaxf(fmaxf(r0, r1), fmaxf(x64v, x65v));
    float L   = 0.f;
    __syncwarp();

    const int dE = w ? -TT : TT;
    const float* emrow = esh[w] + (w ? 62*TT : TT);

    // ---- one step; if apply: finish deferred renorm (butterfly overlaps fma) ----
    auto STEP = [&](bool apply) {
        float scl = 1.0f;
        if (apply) {
            float m = mmp;
            m = fmaxf(m, __shfl_xor_sync(~0u, m, 1));
            m = fmaxf(m, __shfl_xor_sync(~0u, m, 2));
            m = fmaxf(m, __shfl_xor_sync(~0u, m, 4));
            m = fmaxf(m, __shfl_xor_sync(~0u, m, 8));
            m = fmaxf(m, __shfl_xor_sync(~0u, m, 16));
            scl = __fdividef(1.0f, m);
            L  += __logf(m);
        }
        float2 em  = ((const float2*)emrow)[lane];
        float2 emx = *(const float2*)(emrow + 64);
        ull x01 = pk2(x64v, x65v);               // pair 32 from registers
        // extra states: group-redundant partial over 8 pairs, butterfly early
        const ulonglong2* ux = (const ulonglong2*)(uc + 8*g);
        ulonglong2 va0 = ux[0], va1 = ux[1];
        ull XA = 0, XB = 0;
        fma2(XA, va0.x, xA[0]); fma2(XB, va0.x, xB[0]);
        fma2(XA, va0.y, xA[1]); fma2(XB, va0.y, xB[1]);
        fma2(XA, va1.x, xA[2]); fma2(XB, va1.x, xB[2]);
        fma2(XA, va1.y, xA[3]); fma2(XB, va1.y, xB[3]);
        float2 fa = upk2(XA), fb = upk2(XB);
        float px = fa.x + fb.y;
        float py = fa.y + fb.x;
        px += __shfl_xor_sync(~0u, px, 1);  py += __shfl_xor_sync(~0u, py, 1);
        px += __shfl_xor_sync(~0u, px, 2);  py += __shfl_xor_sync(~0u, py, 2);
        px += __shfl_xor_sync(~0u, px, 4);  py += __shfl_xor_sync(~0u, py, 4);
        px += x64v*cx0 + x65v*cx1;
        py += x64v*cy0 + x65v*cy1;
        // main dot (smem broadcast)
        const ulonglong2* up = (const ulonglong2*)uc;
        ull dA0 = 0, dA1 = 0, dB0 = 0, dB1 = 0;
        #pragma unroll
        for (int i = 0; i < 16; i++) {
            ulonglong2 va = up[i];
            fma2(dA0, va.x, eA[2*i]);   fma2(dB0, va.x, eB[2*i]);
            fma2(dA1, va.y, eA[2*i+1]); fma2(dB1, va.y, eB[2*i+1]);
        }
        fma2(dA0, x01, eA[32]);
        fma2(dB0, x01, eB[32]);
        add2(dA0, dA0, dA1); add2(dB0, dB0, dB1);
        float2 A = upk2(dA0), Bv = upk2(dB0);
        r0   = (A.x + Bv.y) * (scl * em.x);
        r1   = (A.y + Bv.x) * (scl * em.y);
        x64v = px * (scl * emx.x);
        x65v = py * (scl * emx.y);
        CFENCE();
        ((float2*)un)[lane] = make_float2(r0, r1);
        CFENCE();
        float* tp = uc; uc = un; un = tp;
        emrow += dE;
    };

    // ---- 63 steps: 7 groups of 8 + tail 7; renorm applied at group starts ----
    for (int grp = 0; grp < 8; grp++) {
        const int n = (grp == 7) ? 7 : 8;
        #pragma unroll 8
        for (int q = 0; q < n; q++) {
            STEP(q == 0);
            if (q == n-1 && grp < 7)
                mmp = fmaxf(fmaxf(r0, r1), fmaxf(x64v, x65v));
        }
    }
    // invariant: actual = stored * exp(L)   (no pending scale)

    // ---- chains meet ----
    if (w == 1) {
        ((float2*)wslab)[lane] = make_float2(r0, r1);
        if (lane == 0) {
            *(float2*)(wslab + 64) = make_float2(x64v, x65v);
            sL[1] = L;
        }
    } else if (lane == 0) {
        sL[0] = L;
    }
    __syncthreads();

    // ---- epilogue (warp 0): Z = sum_j (alpha_63 M)[j] * w_64[j] ----
    if (w == 0) {
        ull x01 = pk2(x64v, x65v);
        const ulonglong2* ux = (const ulonglong2*)(uc + 8*g);
        ulonglong2 va0 = ux[0], va1 = ux[1];
        ull XA = 0, XB = 0;
        fma2(XA, va0.x, xA[0]); fma2(XB, va0.x, xB[0]);
        fma2(XA, va0.y, xA[1]); fma2(XB, va0.y, xB[1]);
        fma2(XA, va1.x, xA[2]); fma2(XB, va1.x, xB[2]);
        fma2(XA, va1.y, xA[3]); fma2(XB, va1.y, xB[3]);
        float2 fa = upk2(XA), fb = upk2(XB);
        float px = fa.x + fb.y;
        float py = fa.y + fb.x;
        px += __shfl_xor_sync(~0u, px, 1);  py += __shfl_xor_sync(~0u, py, 1);
        px += __shfl_xor_sync(~0u, px, 2);  py += __shfl_xor_sync(~0u, py, 2);
        px += __shfl_xor_sync(~0u, px, 4);  py += __shfl_xor_sync(~0u, py, 4);
        px += x64v*cx0 + x65v*cx1;
        py += x64v*cy0 + x65v*cy1;
        const ulonglong2* up = (const ulonglong2*)uc;
        ull dA0 = 0, dA1 = 0, dB0 = 0, dB1 = 0;
        #pragma unroll
        for (int i = 0; i < 16; i++) {
            ulonglong2 va = up[i];
            fma2(dA0, va.x, eA[2*i]);   fma2(dB0, va.x, eB[2*i]);
            fma2(dA1, va.y, eA[2*i+1]); fma2(dB1, va.y, eB[2*i+1]);
        }
        fma2(dA0, x01, eA[32]);
        fma2(dB0, x01, eB[32]);
        add2(dA0, dA0, dA1); add2(dB0, dB0, dB1);
        float2 A = upk2(dA0), Bv = upk2(dB0);
        float2 wv = ((const float2*)wslab)[lane];
        float contrib = (A.x + Bv.y) * wv.x + (A.y + Bv.x) * wv.y;
        if (lane == 0)
            contrib += px*wslab[64] + py*wslab[65];
        #pragma unroll
        for (int o = 16; o; o >>= 1) contrib += __shfl_xor_sync(~0u, contrib, o);
        if (lane == 0) swsum = contrib;
    }
    __syncthreads();

    if (tid == 0) {
        float logZ = __logf(swsum) + sL[0] + sL[1];
        __stcg(&g_partial[seq], logZ - (sgold[0] + sgold[1]));
        __threadfence();
        unsigned c0 = atomicAdd(&g_count, 1u);
        sflag = (c0 == NSEQ - 1) ? 1 : 0;
    }
    __syncthreads();

    // ---- fused final reduction in the last block ----
    if (sflag) {
        float v = 0.f;
        #pragma unroll
        for (int p = 0; p < 4; p++) v += __ldcg(&g_partial[tid + 64*p]);
        #pragma unroll
        for (int o = 16; o; o >>= 1) v += __shfl_xor_sync(~0u, v, o);
        if (lane == 0) wred[w] = v;
        __syncthreads();
        if (tid == 0) {
            out[0] = (wred[0] + wred[1]) * (1.0f / (float)NSEQ);
            g_count = 0;                   // reset for next graph replay
        }
    }
}

extern "C" void kernel_launch(void* const* d_in, const int* in_sizes, int n_in,
                              void* d_out, int out_size) {
    const float* score      = (const float*)d_in[0];
    const float* trans      = (const float*)d_in[1];
    const float* startT     = (const float*)d_in[2];
    const float* endT       = (const float*)d_in[3];
    const int*   v_label    = (const int*)d_in[4];
    const int*   role_label = (const int*)d_in[5];
    float* out = (float*)d_out;

    crf_kernel<<<NSEQ, NTHR>>>(score, trans, startT, endT, v_label, role_label, out);
}